// round 2
// baseline (speedup 1.0000x reference)
#include <cuda_runtime.h>
#include <cuda_bf16.h>
#include <math_constants.h>

#define C_CLASSES 1000
#define DIMS      512
#define CT_STRIDE 1024           // padded column count of transposed centers
#define N_MAX     262144
#define MARGIN_INTER 1.0f

// ---------------- device scratch (static; no runtime allocation) ----------------
__device__ int      g_counts[C_CLASSES];
__device__ int      g_offsets[C_CLASSES];
__device__ int      g_cursor[C_CLASSES];
__device__ int      g_rowidx[N_MAX];
__device__ float    g_centersT[DIMS * CT_STRIDE];  // [D][1024]; cols >= C stay 0 (static init)
__device__ float    g_sq[C_CLASSES];
__device__ unsigned g_minbits;
__device__ int      g_lab64;                       // 1 if labels are int64, else int32

// label fetch that works for both int32 and int64 (little-endian, labels < 1000)
__device__ __forceinline__ int get_lab(const int* __restrict__ lab32, int r, int is64) {
    return is64 ? lab32[2 * r] : lab32[r];
}

// ---------------- kernel 0: init + dtype sniff ----------------
__global__ void k_init(const int* __restrict__ lab32, int N) {
    const int t = threadIdx.x;
    for (int i = t; i < C_CLASSES; i += blockDim.x) g_counts[i] = 0;
    if (t == 0) {
        g_minbits = 0x7f800000u;  // +inf
        int odd_or = 0;
        const int m = (N < 16) ? N : 16;
        for (int i = 0; i < m; i++) odd_or |= lab32[2 * i + 1];
        g_lab64 = (odd_or == 0) ? 1 : 0;
    }
}

// ---------------- kernel 1: label histogram (smem-privatized) ----------------
__global__ __launch_bounds__(256) void k_count(const int* __restrict__ lab32, int N) {
    __shared__ int scnt[C_CLASSES];
    const int tid = threadIdx.x;
    for (int i = tid; i < C_CLASSES; i += 256) scnt[i] = 0;
    __syncthreads();
    const int is64 = g_lab64;
    for (int r = blockIdx.x * 256 + tid; r < N; r += gridDim.x * 256)
        atomicAdd(&scnt[get_lab(lab32, r, is64)], 1);
    __syncthreads();
    for (int i = tid; i < C_CLASSES; i += 256)
        if (scnt[i]) atomicAdd(&g_counts[i], scnt[i]);
}

// ---------------- kernel 2: exclusive scan over 1000 counts (1 block) ----------------
__global__ __launch_bounds__(1024) void k_scan() {
    __shared__ int buf[1024];
    const int t = threadIdx.x;
    const int v = (t < C_CLASSES) ? g_counts[t] : 0;
    buf[t] = v;
    __syncthreads();
    #pragma unroll
    for (int off = 1; off < 1024; off <<= 1) {
        const int x = (t >= off) ? buf[t - off] : 0;
        __syncthreads();
        buf[t] += x;
        __syncthreads();
    }
    if (t < C_CLASSES) {
        const int excl = buf[t] - v;
        g_offsets[t] = excl;
        g_cursor[t]  = excl;
    }
}

// ---------------- kernel 3: scatter row indices into class buckets ----------------
__global__ __launch_bounds__(256) void k_scatter(const int* __restrict__ lab32, int N) {
    const int is64 = g_lab64;
    for (int r = blockIdx.x * 256 + threadIdx.x; r < N; r += gridDim.x * 256) {
        const int lab = get_lab(lab32, r, is64);
        const int pos = atomicAdd(&g_cursor[lab], 1);
        g_rowidx[pos] = r;
    }
}

// ---------------- kernel 4: gather-mean per class -> centersT + sq ----------------
// one block per class, 256 threads; thread t owns dims 2t, 2t+1.
// No float atomics anywhere: rows of a class are summed in registers.
__global__ __launch_bounds__(256) void k_gather(const float* __restrict__ feat) {
    const int c   = blockIdx.x;
    const int tid = threadIdx.x;
    const int start = g_offsets[c];
    const int cnt   = g_counts[c];
    const int* __restrict__ ridx = &g_rowidx[start];

    float2 a0 = {0.f, 0.f}, a1 = {0.f, 0.f}, a2 = {0.f, 0.f}, a3 = {0.f, 0.f};
    const int col = 2 * tid;

    int i = 0;
    for (; i + 4 <= cnt; i += 4) {
        const long long r0 = ridx[i], r1 = ridx[i + 1], r2 = ridx[i + 2], r3 = ridx[i + 3];
        const float2 v0 = *reinterpret_cast<const float2*>(&feat[r0 * DIMS + col]);
        const float2 v1 = *reinterpret_cast<const float2*>(&feat[r1 * DIMS + col]);
        const float2 v2 = *reinterpret_cast<const float2*>(&feat[r2 * DIMS + col]);
        const float2 v3 = *reinterpret_cast<const float2*>(&feat[r3 * DIMS + col]);
        a0.x += v0.x; a0.y += v0.y;
        a1.x += v1.x; a1.y += v1.y;
        a2.x += v2.x; a2.y += v2.y;
        a3.x += v3.x; a3.y += v3.y;
    }
    for (; i < cnt; i++) {
        const long long r = ridx[i];
        const float2 v = *reinterpret_cast<const float2*>(&feat[r * DIMS + col]);
        a0.x += v.x; a0.y += v.y;
    }

    const float inv = 1.0f / fmaxf((float)cnt, 1.0f);
    const float c0 = (a0.x + a1.x + a2.x + a3.x) * inv;
    const float c1 = (a0.y + a1.y + a2.y + a3.y) * inv;
    g_centersT[(col    ) * CT_STRIDE + c] = c0;
    g_centersT[(col + 1) * CT_STRIDE + c] = c1;

    float sq = fmaf(c0, c0, c1 * c1);
    #pragma unroll
    for (int o = 16; o > 0; o >>= 1) sq += __shfl_down_sync(0xffffffffu, sq, o);
    __shared__ float wsum[8];
    if ((tid & 31) == 0) wsum[tid >> 5] = sq;
    __syncthreads();
    if (tid == 0) {
        float s = 0.f;
        #pragma unroll
        for (int w = 0; w < 8; w++) s += wsum[w];
        g_sq[c] = s;
    }
}

// ---------------- kernel 5: triangular pairwise min positive distance ----------------
#define TILE 64
#define KK   16
__global__ __launch_bounds__(256) void k_pairmin() {
    const int nt = (C_CLASSES + TILE - 1) / TILE;  // 16
    int b = blockIdx.x, bi = 0;
    while (b >= nt - bi) { b -= nt - bi; bi++; }
    const int bj = bi + b;
    const int i0 = bi * TILE, j0 = bj * TILE;

    __shared__ float As[KK][TILE];
    __shared__ float Bs[KK][TILE];

    const int tid = threadIdx.x;
    const int ty = tid >> 4, tx = tid & 15;
    const int lkk = tid >> 4, li4 = (tid & 15) * 4;

    float acc[4][4];
    #pragma unroll
    for (int u = 0; u < 4; u++)
        #pragma unroll
        for (int v = 0; v < 4; v++) acc[u][v] = 0.0f;

    for (int k0 = 0; k0 < DIMS; k0 += KK) {
        *reinterpret_cast<float4*>(&As[lkk][li4]) =
            *reinterpret_cast<const float4*>(&g_centersT[(k0 + lkk) * CT_STRIDE + i0 + li4]);
        *reinterpret_cast<float4*>(&Bs[lkk][li4]) =
            *reinterpret_cast<const float4*>(&g_centersT[(k0 + lkk) * CT_STRIDE + j0 + li4]);
        __syncthreads();

        #pragma unroll
        for (int kk = 0; kk < KK; kk++) {
            const float4 a  = *reinterpret_cast<const float4*>(&As[kk][ty * 4]);
            const float4 bb = *reinterpret_cast<const float4*>(&Bs[kk][tx * 4]);
            acc[0][0] = fmaf(a.x, bb.x, acc[0][0]);
            acc[0][1] = fmaf(a.x, bb.y, acc[0][1]);
            acc[0][2] = fmaf(a.x, bb.z, acc[0][2]);
            acc[0][3] = fmaf(a.x, bb.w, acc[0][3]);
            acc[1][0] = fmaf(a.y, bb.x, acc[1][0]);
            acc[1][1] = fmaf(a.y, bb.y, acc[1][1]);
            acc[1][2] = fmaf(a.y, bb.z, acc[1][2]);
            acc[1][3] = fmaf(a.y, bb.w, acc[1][3]);
            acc[2][0] = fmaf(a.z, bb.x, acc[2][0]);
            acc[2][1] = fmaf(a.z, bb.y, acc[2][1]);
            acc[2][2] = fmaf(a.z, bb.z, acc[2][2]);
            acc[2][3] = fmaf(a.z, bb.w, acc[2][3]);
            acc[3][0] = fmaf(a.w, bb.x, acc[3][0]);
            acc[3][1] = fmaf(a.w, bb.y, acc[3][1]);
            acc[3][2] = fmaf(a.w, bb.z, acc[3][2]);
            acc[3][3] = fmaf(a.w, bb.w, acc[3][3]);
        }
        __syncthreads();
    }

    float lmin = CUDART_INF_F;
    #pragma unroll
    for (int u = 0; u < 4; u++) {
        const int gi = i0 + ty * 4 + u;
        if (gi >= C_CLASSES) continue;
        const float sqi = g_sq[gi];
        #pragma unroll
        for (int v = 0; v < 4; v++) {
            const int gj = j0 + tx * 4 + v;
            if (gj >= C_CLASSES) continue;
            const float dis = sqi + g_sq[gj] - 2.0f * acc[u][v];
            if (dis > 0.0f) lmin = fminf(lmin, dis);
        }
    }

    __shared__ float red[256];
    red[tid] = lmin;
    __syncthreads();
    #pragma unroll
    for (int off = 128; off > 0; off >>= 1) {
        if (tid < off) red[tid] = fminf(red[tid], red[tid + off]);
        __syncthreads();
    }
    if (tid == 0) atomicMin(&g_minbits, __float_as_uint(red[0]));
}

// ---------------- kernel 6: final hinge ----------------
__global__ void k_final(float* out) {
    const float dmin = __uint_as_float(g_minbits);
    out[0] = fmaxf(MARGIN_INTER - dmin, 0.0f);  // BETA = 1
}

// ---------------- launch ----------------
extern "C" void kernel_launch(void* const* d_in, const int* in_sizes, int n_in,
                              void* d_out, int out_size) {
    // robust input identification: features is the larger buffer
    int fi = 0, li = 1;
    if (n_in >= 2 && in_sizes[1] > in_sizes[0]) { fi = 1; li = 0; }
    const float* feat  = (const float*)d_in[fi];
    const int*   lab32 = (const int*)d_in[li];
    const int N = in_sizes[li];
    float* out = (float*)d_out;

    k_init<<<1, 1024>>>(lab32, N);
    k_count<<<128, 256>>>(lab32, N);
    k_scan<<<1, 1024>>>();
    k_scatter<<<128, 256>>>(lab32, N);
    k_gather<<<C_CLASSES, 256>>>(feat);
    {
        const int nt = (C_CLASSES + TILE - 1) / TILE;
        k_pairmin<<<nt * (nt + 1) / 2, 256>>>();
    }
    k_final<<<1, 1>>>(out);
}

// round 3
// speedup vs baseline: 1.2242x; 1.2242x over previous
#include <cuda_runtime.h>
#include <cuda_bf16.h>
#include <math_constants.h>

#define C_CLASSES 1000
#define DIMS      512
#define KPAIRS    256            // DIMS/2 packed bf16 pairs per class
#define N_MAX     262144
#define NBLK      128            // count/scatter block partition
#define MARGIN_INTER 1.0f

// ---------------- device scratch (static; zero-initialized at load) ----------------
__device__ int      g_blockcnt[NBLK * C_CLASSES];   // per-block histograms -> bases
__device__ int      g_counts[C_CLASSES];
__device__ int      g_offsets[C_CLASSES];
__device__ int      g_rowidx[N_MAX];
__device__ unsigned g_centers_bf[1024 * KPAIRS];    // [class][kpair] bf16x2; cls>=1000 stay 0
__device__ float    g_sq[C_CLASSES];
__device__ unsigned g_minbits;

// label fetch working for both int32 and int64 (little-endian, labels < 1000)
__device__ __forceinline__ int get_lab(const int* __restrict__ lab32, int r, int is64) {
    return is64 ? lab32[2 * r] : lab32[r];
}
// per-block dtype sniff: int64 labels < 1000 have zero odd words
__device__ __forceinline__ int sniff64(const int* __restrict__ lab32, int N) {
    int odd_or = 0;
    const int m = (N < 16) ? N : 16;
    for (int i = 0; i < m; i++) odd_or |= lab32[2 * i + 1];
    return (odd_or == 0) ? 1 : 0;
}

// ---------------- kernel 1: per-block label histogram (no global atomics) -------
__global__ __launch_bounds__(256) void k_count(const int* __restrict__ lab32, int N) {
    __shared__ int scnt[C_CLASSES];
    const int b = blockIdx.x, tid = threadIdx.x;
    for (int i = tid; i < C_CLASSES; i += 256) scnt[i] = 0;
    const int is64 = sniff64(lab32, N);
    __syncthreads();
    const int rpb = (N + NBLK - 1) / NBLK;
    const int r0 = b * rpb, r1 = min(r0 + rpb, N);
    for (int r = r0 + tid; r < r1; r += 256)
        atomicAdd(&scnt[get_lab(lab32, r, is64)], 1);
    __syncthreads();
    for (int i = tid; i < C_CLASSES; i += 256)
        g_blockcnt[b * C_CLASSES + i] = scnt[i];
}

// ---------------- kernel 2: per-block bases + class exclusive scan (1 block) ----
__global__ __launch_bounds__(1024) void k_scan() {
    const int c = threadIdx.x;
    int total = 0;
    if (c < C_CLASSES) {
        #pragma unroll 8
        for (int b = 0; b < NBLK; b++) {
            const int t = g_blockcnt[b * C_CLASSES + c];
            g_blockcnt[b * C_CLASSES + c] = total;   // in-place -> per-block base
            total += t;
        }
    }
    __shared__ int buf[1024];
    buf[c] = (c < C_CLASSES) ? total : 0;
    __syncthreads();
    #pragma unroll
    for (int off = 1; off < 1024; off <<= 1) {
        const int x = (c >= off) ? buf[c - off] : 0;
        __syncthreads();
        buf[c] += x;
        __syncthreads();
    }
    if (c < C_CLASSES) {
        g_offsets[c] = buf[c] - total;   // exclusive
        g_counts[c]  = total;
    }
    if (c == 0) g_minbits = 0x7f800000u; // +inf reset (every launch)
}

// ---------------- kernel 3: scatter via smem cursors (no global atomics) --------
__global__ __launch_bounds__(256) void k_scatter(const int* __restrict__ lab32, int N) {
    __shared__ int scur[C_CLASSES];
    const int b = blockIdx.x, tid = threadIdx.x;
    for (int i = tid; i < C_CLASSES; i += 256)
        scur[i] = g_blockcnt[b * C_CLASSES + i] + g_offsets[i];
    const int is64 = sniff64(lab32, N);
    __syncthreads();
    const int rpb = (N + NBLK - 1) / NBLK;
    const int r0 = b * rpb, r1 = min(r0 + rpb, N);
    for (int r = r0 + tid; r < r1; r += 256) {
        const int lab = get_lab(lab32, r, is64);
        const int pos = atomicAdd(&scur[lab], 1);
        g_rowidx[pos] = r;
    }
}

// ---------------- kernel 4: gather-mean per class -> bf16 centers + sq ----------
// one block per class, 256 threads; thread t owns dims 2t, 2t+1. No float atomics.
__global__ __launch_bounds__(256) void k_gather(const float* __restrict__ feat) {
    const int c   = blockIdx.x;
    const int tid = threadIdx.x;
    const int start = g_offsets[c];
    const int cnt   = g_counts[c];
    const int* __restrict__ ridx = &g_rowidx[start];

    float2 a0 = {0.f, 0.f}, a1 = {0.f, 0.f}, a2 = {0.f, 0.f}, a3 = {0.f, 0.f};
    const int col = 2 * tid;

    int i = 0;
    for (; i + 4 <= cnt; i += 4) {
        const long long r0 = ridx[i], r1 = ridx[i + 1], r2 = ridx[i + 2], r3 = ridx[i + 3];
        const float2 v0 = *reinterpret_cast<const float2*>(&feat[r0 * DIMS + col]);
        const float2 v1 = *reinterpret_cast<const float2*>(&feat[r1 * DIMS + col]);
        const float2 v2 = *reinterpret_cast<const float2*>(&feat[r2 * DIMS + col]);
        const float2 v3 = *reinterpret_cast<const float2*>(&feat[r3 * DIMS + col]);
        a0.x += v0.x; a0.y += v0.y;
        a1.x += v1.x; a1.y += v1.y;
        a2.x += v2.x; a2.y += v2.y;
        a3.x += v3.x; a3.y += v3.y;
    }
    for (; i < cnt; i++) {
        const long long r = ridx[i];
        const float2 v = *reinterpret_cast<const float2*>(&feat[r * DIMS + col]);
        a0.x += v.x; a0.y += v.y;
    }

    const float inv = 1.0f / fmaxf((float)cnt, 1.0f);
    const float c0 = (a0.x + a1.x + a2.x + a3.x) * inv;
    const float c1 = (a0.y + a1.y + a2.y + a3.y) * inv;

    // round to bf16 ONCE; sq computed from the SAME bf16 values so that the
    // diagonal of the distance matrix is pure fp32-accumulation noise (like ref)
    const __nv_bfloat16 h0 = __float2bfloat16(c0);
    const __nv_bfloat16 h1 = __float2bfloat16(c1);
    const unsigned pack = (unsigned)__bfloat16_as_ushort(h0)
                        | ((unsigned)__bfloat16_as_ushort(h1) << 16);
    g_centers_bf[c * KPAIRS + tid] = pack;
    const float f0 = __bfloat162float(h0);
    const float f1 = __bfloat162float(h1);

    float sq = fmaf(f0, f0, f1 * f1);
    #pragma unroll
    for (int o = 16; o > 0; o >>= 1) sq += __shfl_down_sync(0xffffffffu, sq, o);
    __shared__ float wsum[8];
    if ((tid & 31) == 0) wsum[tid >> 5] = sq;
    __syncthreads();
    if (tid == 0) {
        float s = 0.f;
        #pragma unroll
        for (int w = 0; w < 8; w++) s += wsum[w];
        g_sq[c] = s;
    }
}

// ---------------- kernel 5: triangular pairwise min via bf16 mma.sync -----------
// 64x64 tiles, 8 warps as 4(row)x2(col); each warp: 16 rows x 32 cols
// (4 n-subtiles of m16n8k16), K=512 in 32 steps. Fragments loaded straight
// from L2/L1-resident packed bf16 centers (512 KB) — no smem staging.
__global__ __launch_bounds__(256) void k_pairmin() {
    const int nt = 16;  // 1024/64
    int b = blockIdx.x, bi = 0;
    while (b >= nt - bi) { b -= nt - bi; bi++; }
    const int bj = bi + b;
    const int i0 = bi * 64, j0 = bj * 64;

    const int tid  = threadIdx.x;
    const int w    = tid >> 5, lane = tid & 31;
    const int wr   = w >> 1,   wc   = w & 1;
    const int gid  = lane >> 2, tig = lane & 3;

    const unsigned* __restrict__ cbf = g_centers_bf;
    const int arow0 = (i0 + 16 * wr + gid) * KPAIRS;
    const int arow1 = arow0 + 8 * KPAIRS;
    int brow[4];
    #pragma unroll
    for (int n = 0; n < 4; n++) brow[n] = (j0 + 32 * wc + 8 * n + gid) * KPAIRS;

    float acc[4][4];
    #pragma unroll
    for (int n = 0; n < 4; n++)
        #pragma unroll
        for (int q = 0; q < 4; q++) acc[n][q] = 0.0f;

    #pragma unroll 4
    for (int s = 0; s < 32; s++) {
        const int o = 8 * s + tig;
        const unsigned a0 = cbf[arow0 + o];
        const unsigned a2 = cbf[arow0 + o + 4];
        const unsigned a1 = cbf[arow1 + o];
        const unsigned a3 = cbf[arow1 + o + 4];
        #pragma unroll
        for (int n = 0; n < 4; n++) {
            const unsigned b0 = cbf[brow[n] + o];
            const unsigned b1 = cbf[brow[n] + o + 4];
            asm volatile(
                "mma.sync.aligned.m16n8k16.row.col.f32.bf16.bf16.f32 "
                "{%0,%1,%2,%3}, {%4,%5,%6,%7}, {%8,%9}, {%0,%1,%2,%3};\n"
                : "+f"(acc[n][0]), "+f"(acc[n][1]), "+f"(acc[n][2]), "+f"(acc[n][3])
                : "r"(a0), "r"(a1), "r"(a2), "r"(a3), "r"(b0), "r"(b1));
        }
    }

    // epilogue: dis = sq_i + sq_j - 2*dot; min over strictly positive
    const int r0 = i0 + 16 * wr + gid;
    const int r1 = r0 + 8;
    const float sq0 = (r0 < C_CLASSES) ? g_sq[r0] : 0.f;
    const float sq1 = (r1 < C_CLASSES) ? g_sq[r1] : 0.f;
    float lmin = CUDART_INF_F;
    #pragma unroll
    for (int n = 0; n < 4; n++) {
        const int cc0 = j0 + 32 * wc + 8 * n + 2 * tig;
        const int cc1 = cc0 + 1;
        const float sj0 = (cc0 < C_CLASSES) ? g_sq[cc0] : 0.f;
        const float sj1 = (cc1 < C_CLASSES) ? g_sq[cc1] : 0.f;
        if (r0 < C_CLASSES) {
            if (cc0 < C_CLASSES) { const float d = sq0 + sj0 - 2.0f * acc[n][0]; if (d > 0.f) lmin = fminf(lmin, d); }
            if (cc1 < C_CLASSES) { const float d = sq0 + sj1 - 2.0f * acc[n][1]; if (d > 0.f) lmin = fminf(lmin, d); }
        }
        if (r1 < C_CLASSES) {
            if (cc0 < C_CLASSES) { const float d = sq1 + sj0 - 2.0f * acc[n][2]; if (d > 0.f) lmin = fminf(lmin, d); }
            if (cc1 < C_CLASSES) { const float d = sq1 + sj1 - 2.0f * acc[n][3]; if (d > 0.f) lmin = fminf(lmin, d); }
        }
    }

    __shared__ float red[256];
    red[tid] = lmin;
    __syncthreads();
    #pragma unroll
    for (int off = 128; off > 0; off >>= 1) {
        if (tid < off) red[tid] = fminf(red[tid], red[tid + off]);
        __syncthreads();
    }
    if (tid == 0) atomicMin(&g_minbits, __float_as_uint(red[0]));
}

// ---------------- kernel 6: final hinge ----------------
__global__ void k_final(float* out) {
    const float dmin = __uint_as_float(g_minbits);
    out[0] = fmaxf(MARGIN_INTER - dmin, 0.0f);  // BETA = 1
}

// ---------------- launch ----------------
extern "C" void kernel_launch(void* const* d_in, const int* in_sizes, int n_in,
                              void* d_out, int out_size) {
    int fi = 0, li = 1;
    if (n_in >= 2 && in_sizes[1] > in_sizes[0]) { fi = 1; li = 0; }
    const float* feat  = (const float*)d_in[fi];
    const int*   lab32 = (const int*)d_in[li];
    const int N = in_sizes[li];
    float* out = (float*)d_out;

    k_count<<<NBLK, 256>>>(lab32, N);
    k_scan<<<1, 1024>>>();
    k_scatter<<<NBLK, 256>>>(lab32, N);
    k_gather<<<C_CLASSES, 256>>>(feat);
    k_pairmin<<<136, 256>>>();
    k_final<<<1, 1>>>(out);
}